// round 2
// baseline (speedup 1.0000x reference)
#include <cuda_runtime.h>
#include <cstdint>

// Problem constants
#define B_SZ   8192
#define IN_SZ  512
#define OUT_SZ 512
#define GRID_G 20
#define GP1    21   // grid_size + 1 coefficients per (o,i)

// ---------------------------------------------------------------------------
// Device scratch (static — no allocation allowed):
//   g_Ct : coeffs transposed to [i][g][o]  (o contiguous)     512*21*512*4 = 22 MB
//   g_Wt : base_w transposed to [i][o]                        512*512*4   = 1 MB
//   g_P  : per-(i,b) params {s = silu(xc), u = grid coord}    512*8192*8  = 32 MB
// ---------------------------------------------------------------------------
__device__ float  g_Ct[(size_t)IN_SZ * GP1 * OUT_SZ];
__device__ float  g_Wt[(size_t)IN_SZ * OUT_SZ];
__device__ float2 g_P [(size_t)IN_SZ * B_SZ];

// ---------------------------------------------------------------------------
// Kernel 1: transpose coeffs [o, i, g] -> Ct [i, g, o] and base_w [o,i] -> Wt [i,o]
// Block: one (i, 128-wide o chunk). Reads ~contiguous 84B per thread,
// writes fully coalesced via shared staging.
// ---------------------------------------------------------------------------
__global__ void kan_transpose(const float* __restrict__ coeffs,
                              const float* __restrict__ base_w) {
    const int i  = blockIdx.y;
    const int oc = blockIdx.x * 128;
    const int o  = oc + threadIdx.x;

    __shared__ float sh[GP1][129];  // +1 pad (row-major writes, col reads)

    const float* src = coeffs + (size_t)o * (IN_SZ * GP1) + (size_t)i * GP1;
#pragma unroll
    for (int g = 0; g < GP1; g++)
        sh[g][threadIdx.x] = src[g];

    g_Wt[(size_t)i * OUT_SZ + o] = base_w[(size_t)o * IN_SZ + i];

    __syncthreads();

    for (int j = threadIdx.x; j < GP1 * 128; j += 128) {
        int g = j >> 7;
        int q = j & 127;
        g_Ct[(size_t)i * (GP1 * OUT_SZ) + (size_t)g * OUT_SZ + oc + q] = sh[g][q];
    }
}

// ---------------------------------------------------------------------------
// Kernel 2: per-(b,i) parameters, stored i-major for coalesced staging later.
//   xc = clip(x,-1,1);  s = silu(xc);  u = (xc+1)*10 in [0,20) (clamped so idx<=19)
// 32x32 tile transpose through shared memory: x reads coalesced in i,
// P writes coalesced in b.
// ---------------------------------------------------------------------------
__global__ void kan_params(const float* __restrict__ x) {
    __shared__ float tile[32][33];
    const int b0 = blockIdx.x * 32;
    const int i0 = blockIdx.y * 32;
    const int tx = threadIdx.x & 31;
    const int ty = threadIdx.x >> 5;   // 8 rows of 32

#pragma unroll
    for (int r = ty; r < 32; r += 8)
        tile[r][tx] = x[(size_t)(b0 + r) * IN_SZ + i0 + tx];

    __syncthreads();

#pragma unroll
    for (int r = ty; r < 32; r += 8) {
        float xv = tile[tx][r];
        float xc = fminf(1.0f, fmaxf(-1.0f, xv));
        float s  = xc / (1.0f + __expf(-xc));        // silu
        float u  = fminf((xc + 1.0f) * 10.0f, 19.999998f);
        g_P[(size_t)(i0 + r) * B_SZ + b0 + tx] = make_float2(s, u);
    }
}

// ---------------------------------------------------------------------------
// Kernel 3: main fused gather-GEMM.
//   Tile: 128 b  x  128 o per block, 256 threads, thread tile 16b x 4o.
//   Per i: stage 21x128 coeff rows + base row + 128 params into SMEM,
//   then each warp (one 128-o stripe, 16 b rows):
//     per b:  LDS.64 (params, broadcast) + 2x LDS.128 (c[idx], c[idx+1])
//             + 12 FFMA (spline interp + base term fused).
//   NI=2 i's staged per sync round.
// ---------------------------------------------------------------------------
#define NI 2

__global__ __launch_bounds__(256, 2)
void kan_main(float* __restrict__ out) {
    __shared__ float  sh_c[NI][GP1][128];
    __shared__ float  sh_w[NI][128];
    __shared__ float2 sh_p[NI][128];

    const int ob   = blockIdx.x * 128;     // o tile base
    const int bb   = blockIdx.y * 128;     // b tile base
    const int tid  = threadIdx.x;
    const int lane = tid & 31;
    const int wrp  = tid >> 5;             // 8 warps -> 8 groups of 16 b rows
    const int brow = wrp * 16;

    float4 acc[16];
#pragma unroll
    for (int k = 0; k < 16; k++) acc[k] = make_float4(0.f, 0.f, 0.f, 0.f);

    for (int i0 = 0; i0 < IN_SZ; i0 += NI) {
        __syncthreads();   // protect previous round's SMEM

        // --- stage coefficients: NI*21*32 float4 = 1344 vectors over 256 threads
        for (int j = tid; j < NI * GP1 * 32; j += 256) {
            int sub = (j >= GP1 * 32) ? 1 : 0;
            int rem = j - sub * (GP1 * 32);
            int g   = rem >> 5;
            int q   = rem & 31;
            float4 v = *(const float4*)&g_Ct[(size_t)(i0 + sub) * (GP1 * OUT_SZ)
                                             + (size_t)g * OUT_SZ + ob + q * 4];
            *(float4*)&sh_c[sub][g][q * 4] = v;
        }
        // --- stage base rows: NI*32 float4
        if (tid < NI * 32) {
            int sub = tid >> 5;
            int q   = tid & 31;
            *(float4*)&sh_w[sub][q * 4] =
                *(const float4*)&g_Wt[(size_t)(i0 + sub) * OUT_SZ + ob + q * 4];
        }
        // --- stage params: NI*128 float2, one per thread (coalesced, i-major)
        {
            int sub = tid >> 7;
            int bl  = tid & 127;
            sh_p[sub][bl] = g_P[(size_t)(i0 + sub) * B_SZ + bb + bl];
        }

        __syncthreads();

#pragma unroll
        for (int sub = 0; sub < NI; sub++) {
            const float4 wr = *(const float4*)&sh_w[sub][lane * 4];
#pragma unroll
            for (int k = 0; k < 16; k++) {
                float2 p  = sh_p[sub][brow + k];      // broadcast within warp
                float  u  = p.y;
                int    idx = (int)u;                  // u >= 0 -> trunc == floor
                float  t  = u - (float)idx;
                float  w0 = 1.0f - t;
                const float* cp = &sh_c[sub][idx][lane * 4];
                float4 c0 = *(const float4*)cp;        // C[idx]
                float4 c1 = *(const float4*)(cp + 128);// C[idx+1] (row stride 128)

                acc[k].x = fmaf(w0, c0.x, acc[k].x);
                acc[k].y = fmaf(w0, c0.y, acc[k].y);
                acc[k].z = fmaf(w0, c0.z, acc[k].z);
                acc[k].w = fmaf(w0, c0.w, acc[k].w);
                acc[k].x = fmaf(t, c1.x, acc[k].x);
                acc[k].y = fmaf(t, c1.y, acc[k].y);
                acc[k].z = fmaf(t, c1.z, acc[k].z);
                acc[k].w = fmaf(t, c1.w, acc[k].w);
                acc[k].x = fmaf(p.x, wr.x, acc[k].x);  // base term: silu(x)*Wt
                acc[k].y = fmaf(p.x, wr.y, acc[k].y);
                acc[k].z = fmaf(p.x, wr.z, acc[k].z);
                acc[k].w = fmaf(p.x, wr.w, acc[k].w);
            }
        }
    }

    const int o = ob + lane * 4;
#pragma unroll
    for (int k = 0; k < 16; k++) {
        *(float4*)&out[(size_t)(bb + brow + k) * OUT_SZ + o] = acc[k];
    }
}

// ---------------------------------------------------------------------------
// Launch: inputs in metadata order: x [8192,512], coeffs [512,512,21],
// base_w [512,512]. Output float [8192,512]. All launches on the capture
// stream (default), ordered by stream dependency. No allocation, no sync.
// ---------------------------------------------------------------------------
extern "C" void kernel_launch(void* const* d_in, const int* in_sizes, int n_in,
                              void* d_out, int out_size) {
    const float* x      = (const float*)d_in[0];
    const float* coeffs = (const float*)d_in[1];
    const float* base_w = (const float*)d_in[2];
    float* out = (float*)d_out;

    kan_transpose<<<dim3(OUT_SZ / 128, IN_SZ), 128>>>(coeffs, base_w);
    kan_params   <<<dim3(B_SZ / 32, IN_SZ / 32), 256>>>(x);
    kan_main     <<<dim3(OUT_SZ / 128, B_SZ / 128), 256>>>(out);
}

// round 6
// speedup vs baseline: 2.0858x; 2.0858x over previous
#include <cuda_runtime.h>
#include <cuda_fp16.h>
#include <cstdint>

// ---------------------------------------------------------------------------
// Problem constants
// ---------------------------------------------------------------------------
#define B_SZ   8192
#define IN_SZ  512
#define OUT_SZ 512
#define GP1    21            // grid_size + 1 coefficients per (o,i)
#define KPI    32            // padded k-slots per input feature
#define KTOT   (IN_SZ * KPI) // 16384

// Dense-GEMM reformulation:
//   out[b,o] = sum_k A[b,k] * Cmat[o,k],   k = i*32 + j
//   A[b, i*32+j]   = (j==idx: 1-t), (j==idx+1: t), (j==21: silu(xc)), else 0  (fp16)
//   Cmat[o, i*32+j]= (j<21: coeffs[o,i,j]), (j==21: base_w[o,i]), else 0       (fp16)
// fp32 accumulation via classic mma.sync m16n8k16 (sm_103 baseline tensor path;
// tcgen05 is rejected by this build's ptxas target).

// ---------------------------------------------------------------------------
// Device scratch (static)
// ---------------------------------------------------------------------------
__device__ __half g_Cmat[(size_t)OUT_SZ * KTOT];   // [o][k], 16 MB
__device__ float2 g_P[(size_t)IN_SZ * B_SZ];       // [i][b] : {silu(xc), grid coord u}

// ---------------------------------------------------------------------------
// Helpers
// ---------------------------------------------------------------------------
__device__ __forceinline__ uint32_t smem_u32(const void* p) {
    uint32_t a;
    asm("{ .reg .u64 t; cvta.to.shared.u64 t, %1; cvt.u32.u64 %0, t; }" : "=r"(a) : "l"(p));
    return a;
}
__device__ __forceinline__ uint32_t sw128(uint32_t off) { return off ^ ((off >> 3) & 0x70); }

__device__ __forceinline__ void ldsm_x4(uint32_t addr, uint32_t r[4]) {
    asm volatile("ldmatrix.sync.aligned.m8n8.x4.shared.b16 {%0,%1,%2,%3}, [%4];"
                 : "=r"(r[0]), "=r"(r[1]), "=r"(r[2]), "=r"(r[3]) : "r"(addr));
}
__device__ __forceinline__ void mma16816(float d[4], const uint32_t a[4],
                                         uint32_t b0, uint32_t b1) {
    asm volatile("mma.sync.aligned.m16n8k16.row.col.f32.f16.f16.f32 "
                 "{%0,%1,%2,%3}, {%4,%5,%6,%7}, {%8,%9}, {%0,%1,%2,%3};"
                 : "+f"(d[0]), "+f"(d[1]), "+f"(d[2]), "+f"(d[3])
                 : "r"(a[0]), "r"(a[1]), "r"(a[2]), "r"(a[3]), "r"(b0), "r"(b1));
}

// ---------------------------------------------------------------------------
// Kernel 1: per-(b,i) params, stored i-major ([i][b]) for coalesced staging.
// u = (clip(x)+1)*10 in [0,20].
// ---------------------------------------------------------------------------
__global__ void kan_params(const float* __restrict__ x) {
    __shared__ float tile[32][33];
    const int b0 = blockIdx.x * 32;
    const int i0 = blockIdx.y * 32;
    const int tx = threadIdx.x & 31;
    const int ty = threadIdx.x >> 5;   // 8 rows of 32

#pragma unroll
    for (int r = ty; r < 32; r += 8)
        tile[r][tx] = x[(size_t)(b0 + r) * IN_SZ + i0 + tx];

    __syncthreads();

#pragma unroll
    for (int r = ty; r < 32; r += 8) {
        float xv = tile[tx][r];
        float xc = fminf(1.0f, fmaxf(-1.0f, xv));
        float s  = xc / (1.0f + __expf(-xc));        // silu
        float u  = (xc + 1.0f) * 10.0f;
        g_P[(size_t)(i0 + r) * B_SZ + b0 + tx] = make_float2(s, u);
    }
}

// ---------------------------------------------------------------------------
// Kernel 2: build Cmat fp16 [o][16384]
// ---------------------------------------------------------------------------
__global__ void kan_cmat(const float* __restrict__ coeffs, const float* __restrict__ bw) {
    int g = blockIdx.x * 256 + threadIdx.x;   // [0, 512*512)
    int o = g >> 9, i = g & 511;
    const float* c = coeffs + (size_t)o * (IN_SZ * GP1) + (size_t)i * GP1;
    __half h[KPI];
#pragma unroll
    for (int j = 0; j < GP1; j++) h[j] = __float2half_rn(c[j]);
    h[21] = __float2half_rn(bw[(size_t)o * IN_SZ + i]);
#pragma unroll
    for (int j = 22; j < KPI; j++) h[j] = __ushort_as_half((unsigned short)0);
    uint4* dst = (uint4*)(g_Cmat + (size_t)o * KTOT + (size_t)i * KPI);
    const uint4* src = (const uint4*)h;
#pragma unroll
    for (int v = 0; v < 4; v++) dst[v] = src[v];
}

// ---------------------------------------------------------------------------
// Main GEMM: 256 CTAs (64 b-tiles x 4 o-tiles), CTA tile M=128 x N=128,
// 8 warps, warp tile 64x32.  Stage K=64 (2 features), double buffered.
// SMEM: A[2][128x128B] at 0, B[2][128x128B] at 32768 -> 64 KB, 2 CTAs/SM.
// ---------------------------------------------------------------------------
#define STAGES (IN_SZ / 2)   // 256

__device__ __forceinline__ void genA(char* smem, int buf, int stage, int bb, int tid) {
    const int isub = tid >> 7;              // 0..1 (feature within stage)
    const int bl   = tid & 127;             // b row
    const int i    = stage * 2 + isub;
    float2 pv = g_P[(size_t)i * B_SZ + bb + bl];   // coalesced per half-block
    char* tile = smem + buf * 16384;
    const uint32_t rowoff = (uint32_t)bl * 128 + (uint32_t)isub * 64;
    uint4 z = make_uint4(0, 0, 0, 0);
#pragma unroll
    for (int c2 = 0; c2 < 4; c2++)
        *(uint4*)(tile + sw128(rowoff + c2 * 16)) = z;
    int idx = (int)pv.y;                    // u >= 0 -> trunc == floor
    idx = idx > 19 ? 19 : idx;              // u==20 -> idx=19, t=1
    float t = pv.y - (float)idx;
    *(__half*)(tile + sw128(rowoff + (uint32_t)idx * 2))       = __float2half_rn(1.0f - t);
    *(__half*)(tile + sw128(rowoff + (uint32_t)(idx + 1) * 2)) = __float2half_rn(t);
    *(__half*)(tile + sw128(rowoff + 42))                      = __float2half_rn(pv.x);
}

__device__ __forceinline__ void loadB(uint32_t sb, int buf, int stage, int ob, int tid) {
    const int k0 = stage * 64;
#pragma unroll
    for (int rep = 0; rep < 4; rep++) {
        int q = tid + rep * 256;            // [0,1024): 128 rows x 8 chunks of 16B
        int r = q >> 3;
        int c = q & 7;
        const __half* gp = g_Cmat + (size_t)(ob + r) * KTOT + (k0 + c * 8);
        uint32_t sa = sb + 32768 + buf * 16384 + sw128((uint32_t)r * 128 + (uint32_t)c * 16);
        asm volatile("cp.async.cg.shared.global [%0], [%1], 16;" :: "r"(sa), "l"(gp));
    }
}

__global__ __launch_bounds__(256, 2) void kan_main(float* __restrict__ out) {
    extern __shared__ char smem[];
    uint32_t sb = smem_u32(smem);
    const int tid   = threadIdx.x;
    const int lane  = tid & 31;
    const int wid   = tid >> 5;
    const int warpM = wid >> 2;             // 0..1 -> 64-row b stripe
    const int warpN = wid & 3;              // 0..3 -> 32-col o stripe
    const int ob = blockIdx.x * 128, bb = blockIdx.y * 128;

    float acc[4][4][4];                     // [mtile][ntile][reg]
#pragma unroll
    for (int mt = 0; mt < 4; mt++)
#pragma unroll
        for (int nt = 0; nt < 4; nt++)
#pragma unroll
            for (int v = 0; v < 4; v++) acc[mt][nt][v] = 0.f;

    // ldmatrix lane addressing (shared by A and B tiles): lanes 0-15 -> rows
    // 0-15 at k-chunk 0, lanes 16-31 -> rows 0-15 at k-chunk +16B.
    const uint32_t lrow = lane & 15;
    const uint32_t lkb  = (lane >> 4) * 16;

    // prologue: stage 0 into buffer 0
    genA(smem, 0, 0, bb, tid);
    loadB(sb, 0, 0, ob, tid);
    asm volatile("cp.async.commit_group;");

    for (int s = 0; s < STAGES; s++) {
        const int cb = s & 1, nb = cb ^ 1;
        if (s + 1 < STAGES) {
            genA(smem, nb, s + 1, bb, tid);      // nb free: last read finished at s-1's tail barrier
            loadB(sb, nb, s + 1, ob, tid);
            asm volatile("cp.async.commit_group;");
            asm volatile("cp.async.wait_group 1;");   // current stage's B complete
        } else {
            asm volatile("cp.async.wait_group 0;");
        }
        __syncthreads();                          // A-gen + B visible to all warps

        const uint32_t Ab = sb + cb * 16384;
        const uint32_t Bb = sb + 32768 + cb * 16384;
#pragma unroll
        for (int ks = 0; ks < 4; ks++) {
            uint32_t a[4][4];
#pragma unroll
            for (int mt = 0; mt < 4; mt++) {
                uint32_t row = (uint32_t)(warpM * 64 + mt * 16) + lrow;
                ldsm_x4(Ab + sw128(row * 128 + ks * 32 + lkb), a[mt]);
            }
            uint32_t bf[2][4];
#pragma unroll
            for (int bt = 0; bt < 2; bt++) {
                uint32_t nrow = (uint32_t)(warpN * 32 + bt * 16) + lrow;
                ldsm_x4(Bb + sw128(nrow * 128 + ks * 32 + lkb), bf[bt]);
            }
#pragma unroll
            for (int mt = 0; mt < 4; mt++)
#pragma unroll
                for (int nt = 0; nt < 4; nt++) {
                    int bt = nt >> 1, hi = nt & 1;
                    // bf[bt]: r0=(n0-7,k0-7) r1=(n8-15,k0-7) r2=(n0-7,k8-15) r3=(n8-15,k8-15)
                    mma16816(acc[mt][nt], a[mt], bf[bt][hi], bf[bt][hi + 2]);
                }
        }
        __syncthreads();                          // done reading cb before next gen overwrites
    }

    // epilogue: direct f32 stores (float2 per acc pair)
#pragma unroll
    for (int mt = 0; mt < 4; mt++) {
        int r0 = bb + warpM * 64 + mt * 16 + (lane >> 2);
#pragma unroll
        for (int nt = 0; nt < 4; nt++) {
            int c0 = ob + warpN * 32 + nt * 8 + (lane & 3) * 2;
            *(float2*)&out[(size_t)r0 * OUT_SZ + c0] =
                make_float2(acc[mt][nt][0], acc[mt][nt][1]);
            *(float2*)&out[(size_t)(r0 + 8) * OUT_SZ + c0] =
                make_float2(acc[mt][nt][2], acc[mt][nt][3]);
        }
    }
}

// ---------------------------------------------------------------------------
// Launch: x [8192,512], coeffs [512,512,21], base_w [512,512] -> out f32 [8192,512]
// ---------------------------------------------------------------------------
extern "C" void kernel_launch(void* const* d_in, const int* in_sizes, int n_in,
                              void* d_out, int out_size) {
    const float* x      = (const float*)d_in[0];
    const float* coeffs = (const float*)d_in[1];
    const float* base_w = (const float*)d_in[2];
    float* out = (float*)d_out;

    cudaFuncSetAttribute(kan_main, cudaFuncAttributeMaxDynamicSharedMemorySize, 65536);

    kan_params<<<dim3(B_SZ / 32, IN_SZ / 32), 256>>>(x);
    kan_cmat  <<<(OUT_SZ * IN_SZ) / 256, 256>>>(coeffs, base_w);
    kan_main  <<<dim3(OUT_SZ / 128, B_SZ / 128), 256, 65536>>>(out);
}

// round 8
// speedup vs baseline: 2.4572x; 1.1781x over previous
#include <cuda_runtime.h>
#include <cuda_fp16.h>
#include <cstdint>

// ---------------------------------------------------------------------------
// Problem constants
// ---------------------------------------------------------------------------
#define B_SZ   8192
#define IN_SZ  512
#define OUT_SZ 512
#define GP1    21            // grid_size + 1 coefficients per (o,i)
#define KPI    24            // padded k-slots per input feature (21 coeff + base + 2 pad)
#define KTOT   (IN_SZ * KPI) // 12288
#define STAGES (KTOT / 64)   // 192 stages of K=64

// Dense-GEMM reformulation:
//   out[b,o] = sum_k A[b,k] * Cmat[o,k],   k = i*24 + j
//   A[b, i*24+j]   = (j==idx: 1-t), (j==idx+1: t), (j==21: silu(xc)), else 0  (fp16)
//   Cmat[o, i*24+j]= (j<21: coeffs[o,i,j]), (j==21: base_w[o,i]), else 0       (fp16)
// fp32 accumulation via mma.sync m16n8k16 (plain sm_103 target: no tcgen05/TMA).

// ---------------------------------------------------------------------------
// Device scratch (static)
// ---------------------------------------------------------------------------
__device__ __half g_Cmat[(size_t)OUT_SZ * KTOT];   // [o][k], 12 MB
__device__ float2 g_P[(size_t)IN_SZ * B_SZ];       // [i][b] : {silu(xc), grid coord u}

// ---------------------------------------------------------------------------
// Helpers
// ---------------------------------------------------------------------------
__device__ __forceinline__ uint32_t smem_u32(const void* p) {
    uint32_t a;
    asm("{ .reg .u64 t; cvta.to.shared.u64 t, %1; cvt.u32.u64 %0, t; }" : "=r"(a) : "l"(p));
    return a;
}
__device__ __forceinline__ uint32_t sw128(uint32_t off) { return off ^ ((off >> 3) & 0x70); }

__device__ __forceinline__ void ldsm_x4(uint32_t addr, uint32_t r[4]) {
    asm volatile("ldmatrix.sync.aligned.m8n8.x4.shared.b16 {%0,%1,%2,%3}, [%4];"
                 : "=r"(r[0]), "=r"(r[1]), "=r"(r[2]), "=r"(r[3]) : "r"(addr));
}
__device__ __forceinline__ void mma16816(float d[4], const uint32_t a[4],
                                         uint32_t b0, uint32_t b1) {
    asm volatile("mma.sync.aligned.m16n8k16.row.col.f32.f16.f16.f32 "
                 "{%0,%1,%2,%3}, {%4,%5,%6,%7}, {%8,%9}, {%0,%1,%2,%3};"
                 : "+f"(d[0]), "+f"(d[1]), "+f"(d[2]), "+f"(d[3])
                 : "r"(a[0]), "r"(a[1]), "r"(a[2]), "r"(a[3]), "r"(b0), "r"(b1));
}

// ---------------------------------------------------------------------------
// Kernel 1: per-(b,i) params, stored i-major ([i][b]) for coalesced staging.
// u = (clip(x)+1)*10 in [0,20].
// ---------------------------------------------------------------------------
__global__ void kan_params(const float* __restrict__ x) {
    __shared__ float tile[32][33];
    const int b0 = blockIdx.x * 32;
    const int i0 = blockIdx.y * 32;
    const int tx = threadIdx.x & 31;
    const int ty = threadIdx.x >> 5;   // 8 rows of 32

#pragma unroll
    for (int r = ty; r < 32; r += 8)
        tile[r][tx] = x[(size_t)(b0 + r) * IN_SZ + i0 + tx];

    __syncthreads();

#pragma unroll
    for (int r = ty; r < 32; r += 8) {
        float xv = tile[tx][r];
        float xc = fminf(1.0f, fmaxf(-1.0f, xv));
        float s  = xc / (1.0f + __expf(-xc));        // silu
        float u  = (xc + 1.0f) * 10.0f;
        g_P[(size_t)(i0 + r) * B_SZ + b0 + tx] = make_float2(s, u);
    }
}

// ---------------------------------------------------------------------------
// Kernel 2: build Cmat fp16 [o][12288]; 24 halves = 48B = 3x16B per (o,i)
// ---------------------------------------------------------------------------
__global__ void kan_cmat(const float* __restrict__ coeffs, const float* __restrict__ bw) {
    int g = blockIdx.x * 256 + threadIdx.x;   // [0, 512*512)
    int o = g >> 9, i = g & 511;
    const float* c = coeffs + (size_t)o * (IN_SZ * GP1) + (size_t)i * GP1;
    __half h[KPI];
#pragma unroll
    for (int j = 0; j < GP1; j++) h[j] = __float2half_rn(c[j]);
    h[21] = __float2half_rn(bw[(size_t)o * IN_SZ + i]);
    h[22] = __ushort_as_half((unsigned short)0);
    h[23] = __ushort_as_half((unsigned short)0);
    uint4* dst = (uint4*)(g_Cmat + (size_t)o * KTOT + (size_t)i * KPI);
    const uint4* src = (const uint4*)h;
#pragma unroll
    for (int v = 0; v < 3; v++) dst[v] = src[v];
}

// ---------------------------------------------------------------------------
// Main GEMM: 256 CTAs (64 b-tiles x 4 o-tiles), CTA tile M=128 x N=128,
// 4 warps (128 threads), warp tile 64x64.  Stage K=64, double buffered.
// SMEM: A[2][128x128B] at 0, B[2][128x128B] at 32768 -> 64 KB, 2 CTAs/SM.
// ---------------------------------------------------------------------------

// A-gen: thread t owns SMEM row t (one b). Features straddle the K=64 stage
// window (KPI=24 < 64): up to 4 features overlap [64s, 64s+64); each
// contributes <=3 predicated half-stores.
__device__ __forceinline__ void genA(char* smem, int buf, int stage, int bb, int tid) {
    char* tile = smem + buf * 16384;
    const uint32_t rowoff = (uint32_t)tid * 128;
    uint4 z = make_uint4(0, 0, 0, 0);
#pragma unroll
    for (int c = 0; c < 8; c++)
        *(uint4*)(tile + sw128(rowoff + c * 16)) = z;

    const int k0   = stage * 64;
    const int i_lo = k0 / KPI;
#pragma unroll
    for (int f = 0; f < 4; f++) {
        int i = i_lo + f;
        if (i < IN_SZ) {
            float2 pv = g_P[(size_t)i * B_SZ + bb + tid];    // coalesced
            int idx = (int)pv.y;                             // u >= 0
            idx = idx > 19 ? 19 : idx;                       // u==20 -> idx=19, t=1
            float t = pv.y - (float)idx;
            int kbase = i * KPI - k0;                        // stage-local slot 0
            int k1 = kbase + idx;                            // 1-t
            int k2 = k1 + 1;                                 // t
            int k3 = kbase + 21;                             // silu
            if ((unsigned)k1 < 64u)
                *(__half*)(tile + sw128(rowoff + (uint32_t)k1 * 2)) = __float2half_rn(1.0f - t);
            if ((unsigned)k2 < 64u)
                *(__half*)(tile + sw128(rowoff + (uint32_t)k2 * 2)) = __float2half_rn(t);
            if ((unsigned)k3 < 64u)
                *(__half*)(tile + sw128(rowoff + (uint32_t)k3 * 2)) = __float2half_rn(pv.x);
        }
    }
}

__device__ __forceinline__ void loadB(uint32_t sb, int buf, int stage, int ob, int tid) {
    const int k0 = stage * 64;
#pragma unroll
    for (int rep = 0; rep < 8; rep++) {
        int q = tid + rep * 128;            // [0,1024): 128 rows x 8 chunks of 16B
        int r = q >> 3;
        int c = q & 7;
        const __half* gp = g_Cmat + (size_t)(ob + r) * KTOT + (k0 + c * 8);
        uint32_t sa = sb + 32768 + buf * 16384 + sw128((uint32_t)r * 128 + (uint32_t)c * 16);
        asm volatile("cp.async.cg.shared.global [%0], [%1], 16;" :: "r"(sa), "l"(gp));
    }
}

__global__ __launch_bounds__(128, 2) void kan_main(float* __restrict__ out) {
    extern __shared__ char smem[];
    uint32_t sb = smem_u32(smem);
    const int tid   = threadIdx.x;
    const int lane  = tid & 31;
    const int wid   = tid >> 5;
    const int warpM = wid >> 1;             // 0..1 -> 64-row b stripe
    const int warpN = wid & 1;              // 0..1 -> 64-col o stripe
    const int ob = blockIdx.x * 128, bb = blockIdx.y * 128;

    float acc[4][8][4];                     // [mtile 16r][ntile 8c][reg]
#pragma unroll
    for (int mt = 0; mt < 4; mt++)
#pragma unroll
        for (int nt = 0; nt < 8; nt++)
#pragma unroll
            for (int v = 0; v < 4; v++) acc[mt][nt][v] = 0.f;

    const uint32_t lrow = lane & 15;
    const uint32_t lkb  = (lane >> 4) * 16;

    // prologue: stage 0 into buffer 0
    genA(smem, 0, 0, bb, tid);
    loadB(sb, 0, 0, ob, tid);
    asm volatile("cp.async.commit_group;");

    for (int s = 0; s < STAGES; s++) {
        const int cb = s & 1, nb = cb ^ 1;
        if (s + 1 < STAGES) {
            genA(smem, nb, s + 1, bb, tid);   // nb free: reads done at s-1 tail barrier
            loadB(sb, nb, s + 1, ob, tid);
            asm volatile("cp.async.commit_group;");
            asm volatile("cp.async.wait_group 1;");   // current stage's B complete
        } else {
            asm volatile("cp.async.wait_group 0;");
        }
        __syncthreads();                      // A-gen + B visible to all warps

        const uint32_t Ab = sb + cb * 16384;
        const uint32_t Bb = sb + 32768 + cb * 16384;
#pragma unroll
        for (int ks = 0; ks < 4; ks++) {
            uint32_t a[4][4];
#pragma unroll
            for (int mt = 0; mt < 4; mt++) {
                uint32_t row = (uint32_t)(warpM * 64 + mt * 16) + lrow;
                ldsm_x4(Ab + sw128(row * 128 + ks * 32 + lkb), a[mt]);
            }
            uint32_t bf[4][4];
#pragma unroll
            for (int bt = 0; bt < 4; bt++) {
                uint32_t nrow = (uint32_t)(warpN * 64 + bt * 16) + lrow;
                ldsm_x4(Bb + sw128(nrow * 128 + ks * 32 + lkb), bf[bt]);
            }
#pragma unroll
            for (int mt = 0; mt < 4; mt++)
#pragma unroll
                for (int nt = 0; nt < 8; nt++) {
                    int bt = nt >> 1, hi = nt & 1;
                    mma16816(acc[mt][nt], a[mt], bf[bt][hi], bf[bt][hi + 2]);
                }
        }
        __syncthreads();                      // done reading cb before next gen overwrites
    }

    // epilogue: direct f32 stores
#pragma unroll
    for (int mt = 0; mt < 4; mt++) {
        int r0 = bb + warpM * 64 + mt * 16 + (lane >> 2);
#pragma unroll
        for (int nt = 0; nt < 8; nt++) {
            int c0 = ob + warpN * 64 + nt * 8 + (lane & 3) * 2;
            *(float2*)&out[(size_t)r0 * OUT_SZ + c0] =
                make_float2(acc[mt][nt][0], acc[mt][nt][1]);
            *(float2*)&out[(size_t)(r0 + 8) * OUT_SZ + c0] =
                make_float2(acc[mt][nt][2], acc[mt][nt][3]);
        }
    }
}

// ---------------------------------------------------------------------------
// Launch: x [8192,512], coeffs [512,512,21], base_w [512,512] -> out f32 [8192,512]
// ---------------------------------------------------------------------------
extern "C" void kernel_launch(void* const* d_in, const int* in_sizes, int n_in,
                              void* d_out, int out_size) {
    const float* x      = (const float*)d_in[0];
    const float* coeffs = (const float*)d_in[1];
    const float* base_w = (const float*)d_in[2];
    float* out = (float*)d_out;

    cudaFuncSetAttribute(kan_main, cudaFuncAttributeMaxDynamicSharedMemorySize, 65536);

    kan_params<<<dim3(B_SZ / 32, IN_SZ / 32), 256>>>(x);
    kan_cmat  <<<(OUT_SZ * IN_SZ) / 256, 256>>>(coeffs, base_w);
    kan_main  <<<dim3(OUT_SZ / 128, B_SZ / 128), 128, 65536>>>(out);
}

// round 9
// speedup vs baseline: 2.7867x; 1.1341x over previous
#include <cuda_runtime.h>
#include <cuda_fp16.h>
#include <cstdint>

// ---------------------------------------------------------------------------
// Problem constants
// ---------------------------------------------------------------------------
#define B_SZ   8192
#define IN_SZ  512
#define OUT_SZ 512
#define GP1    21            // grid_size + 1 coefficients per (o,i)
#define KPI    22            // k-slots per input feature (21 coeff + base, no pad)
#define KTOT   (IN_SZ * KPI) // 11264
#define STAGES (KTOT / 64)   // 176 stages of K=64

// Dense-GEMM reformulation:
//   out[b,o] = sum_k A[b,k] * Cmat[o,k],   k = i*22 + j
//   A[b, i*22+j]   = (j==idx: 1-t), (j==idx+1: t), (j==21: silu(xc)), else 0  (fp16)
//   Cmat[o, i*22+j]= (j<21: coeffs[o,i,j]), (j==21: base_w[o,i])               (fp16)
// fp32 accumulation via mma.sync m16n8k16 (legacy tensor path; ~280 TF/s chip
// ceiling measured — this round minimizes K and maximizes issue efficiency).

// ---------------------------------------------------------------------------
// Device scratch (static)
// ---------------------------------------------------------------------------
__device__ __half g_Cmat[(size_t)OUT_SZ * KTOT];   // [o][k], 11.5 MB
__device__ float2 g_P[(size_t)IN_SZ * B_SZ];       // [i][b] : {silu(xc), grid coord u}

// ---------------------------------------------------------------------------
// Helpers
// ---------------------------------------------------------------------------
__device__ __forceinline__ uint32_t smem_u32(const void* p) {
    uint32_t a;
    asm("{ .reg .u64 t; cvta.to.shared.u64 t, %1; cvt.u32.u64 %0, t; }" : "=r"(a) : "l"(p));
    return a;
}
__device__ __forceinline__ uint32_t sw128(uint32_t off) { return off ^ ((off >> 3) & 0x70); }

__device__ __forceinline__ void ldsm_x4(uint32_t addr, uint32_t r[4]) {
    asm volatile("ldmatrix.sync.aligned.m8n8.x4.shared.b16 {%0,%1,%2,%3}, [%4];"
                 : "=r"(r[0]), "=r"(r[1]), "=r"(r[2]), "=r"(r[3]) : "r"(addr));
}
__device__ __forceinline__ void mma16816(float d[4], const uint32_t a[4],
                                         uint32_t b0, uint32_t b1) {
    asm volatile("mma.sync.aligned.m16n8k16.row.col.f32.f16.f16.f32 "
                 "{%0,%1,%2,%3}, {%4,%5,%6,%7}, {%8,%9}, {%0,%1,%2,%3};"
                 : "+f"(d[0]), "+f"(d[1]), "+f"(d[2]), "+f"(d[3])
                 : "r"(a[0]), "r"(a[1]), "r"(a[2]), "r"(a[3]), "r"(b0), "r"(b1));
}

// ---------------------------------------------------------------------------
// Kernel 1: per-(b,i) params, stored i-major ([i][b]) for coalesced staging.
// u = (clip(x)+1)*10 in [0,20].
// ---------------------------------------------------------------------------
__global__ void kan_params(const float* __restrict__ x) {
    __shared__ float tile[32][33];
    const int b0 = blockIdx.x * 32;
    const int i0 = blockIdx.y * 32;
    const int tx = threadIdx.x & 31;
    const int ty = threadIdx.x >> 5;   // 8 rows of 32

#pragma unroll
    for (int r = ty; r < 32; r += 8)
        tile[r][tx] = x[(size_t)(b0 + r) * IN_SZ + i0 + tx];

    __syncthreads();

#pragma unroll
    for (int r = ty; r < 32; r += 8) {
        float xv = tile[tx][r];
        float xc = fminf(1.0f, fmaxf(-1.0f, xv));
        float s  = xc / (1.0f + __expf(-xc));        // silu
        float u  = (xc + 1.0f) * 10.0f;
        g_P[(size_t)(i0 + r) * B_SZ + b0 + tx] = make_float2(s, u);
    }
}

// ---------------------------------------------------------------------------
// Kernel 2: build Cmat fp16 [o][11264], k-linear: each thread emits one 16B
// chunk (8 halves), features straddle chunks freely.
// ---------------------------------------------------------------------------
__global__ void kan_cmat(const float* __restrict__ coeffs, const float* __restrict__ bw) {
    int gch = blockIdx.x * 256 + threadIdx.x;     // [0, 512*1408)
    int o  = gch / (KTOT / 8);
    int ch = gch - o * (KTOT / 8);
    int k0 = ch * 8;
    __half h[8];
#pragma unroll
    for (int v = 0; v < 8; v++) {
        int k = k0 + v;
        int i = k / KPI;
        int j = k - i * KPI;
        float val = (j < GP1) ? coeffs[(size_t)o * (IN_SZ * GP1) + (size_t)i * GP1 + j]
                              : bw[(size_t)o * IN_SZ + i];
        h[v] = __float2half_rn(val);
    }
    *(uint4*)(g_Cmat + (size_t)o * KTOT + k0) = *(const uint4*)h;
}

// ---------------------------------------------------------------------------
// Main GEMM: 256 CTAs (64 b-tiles x 4 o-tiles), CTA tile M=128 x N=128,
// 8 warps (256 threads), warp tile 64x32 (2M x 4N). Stage K=64, double
// buffered. SMEM: A[2][128x128B] at 0, B[2][128x128B] at 32768 -> 64 KB,
// 2 CTAs/SM (16 warps/SM for latency hiding at the HMMA issue ceiling).
// Producer split: threads 0-127 generate A rows; threads 128-255 cp.async B.
// ---------------------------------------------------------------------------

// A-gen: thread t (<128) owns SMEM row t (one b). With KPI=22 < 64, up to 4
// features overlap the window [64s, 64s+64); each contributes <=3 predicated
// half-stores.
__device__ __forceinline__ void genA(char* smem, int buf, int stage, int bb, int row) {
    char* tile = smem + buf * 16384;
    const uint32_t rowoff = (uint32_t)row * 128;
    uint4 z = make_uint4(0, 0, 0, 0);
#pragma unroll
    for (int c = 0; c < 8; c++)
        *(uint4*)(tile + sw128(rowoff + c * 16)) = z;

    const int k0   = stage * 64;
    const int i_lo = k0 / KPI;
#pragma unroll
    for (int f = 0; f < 4; f++) {
        int i = i_lo + f;
        if (i < IN_SZ) {
            float2 pv = g_P[(size_t)i * B_SZ + bb + row];    // coalesced
            int idx = (int)pv.y;                             // u >= 0
            idx = idx > 19 ? 19 : idx;                       // u==20 -> idx=19, t=1
            float t = pv.y - (float)idx;
            int kbase = i * KPI - k0;                        // stage-local slot 0
            int k1 = kbase + idx;                            // 1-t
            int k2 = k1 + 1;                                 // t
            int k3 = kbase + 21;                             // silu
            if ((unsigned)k1 < 64u)
                *(__half*)(tile + sw128(rowoff + (uint32_t)k1 * 2)) = __float2half_rn(1.0f - t);
            if ((unsigned)k2 < 64u)
                *(__half*)(tile + sw128(rowoff + (uint32_t)k2 * 2)) = __float2half_rn(t);
            if ((unsigned)k3 < 64u)
                *(__half*)(tile + sw128(rowoff + (uint32_t)k3 * 2)) = __float2half_rn(pv.x);
        }
    }
}

// B-load: thread t (>=128) issues 8 cp.async of 16B each.
__device__ __forceinline__ void loadB(uint32_t sb, int buf, int stage, int ob, int t2) {
    const int k0 = stage * 64;
#pragma unroll
    for (int rep = 0; rep < 8; rep++) {
        int q = t2 + rep * 128;             // [0,1024): 128 rows x 8 chunks of 16B
        int r = q >> 3;
        int c = q & 7;
        const __half* gp = g_Cmat + (size_t)(ob + r) * KTOT + (k0 + c * 8);
        uint32_t sa = sb + 32768 + buf * 16384 + sw128((uint32_t)r * 128 + (uint32_t)c * 16);
        asm volatile("cp.async.cg.shared.global [%0], [%1], 16;" :: "r"(sa), "l"(gp));
    }
}

__global__ __launch_bounds__(256, 2) void kan_main(float* __restrict__ out) {
    extern __shared__ char smem[];
    uint32_t sb = smem_u32(smem);
    const int tid   = threadIdx.x;
    const int lane  = tid & 31;
    const int wid   = tid >> 5;
    const int warpM = wid >> 2;             // 0..1 -> 64-row b stripe
    const int warpN = wid & 3;              // 0..3 -> 32-col o stripe
    const int ob = blockIdx.x * 128, bb = blockIdx.y * 128;

    float acc[4][4][4];                     // [mtile 16r][ntile 8c][reg]
#pragma unroll
    for (int mt = 0; mt < 4; mt++)
#pragma unroll
        for (int nt = 0; nt < 4; nt++)
#pragma unroll
            for (int v = 0; v < 4; v++) acc[mt][nt][v] = 0.f;

    const uint32_t lrow = lane & 15;
    const uint32_t lkb  = (lane >> 4) * 16;

    // prologue: stage 0 into buffer 0
    if (tid < 128) genA(smem, 0, 0, bb, tid);
    else           loadB(sb, 0, 0, ob, tid - 128);
    asm volatile("cp.async.commit_group;");

    for (int s = 0; s < STAGES; s++) {
        const int cb = s & 1, nb = cb ^ 1;
        if (s + 1 < STAGES) {
            // nb free: its readers finished at stage s-1's tail barrier
            if (tid < 128) genA(smem, nb, s + 1, bb, tid);
            else           loadB(sb, nb, s + 1, ob, tid - 128);
            asm volatile("cp.async.commit_group;");
            asm volatile("cp.async.wait_group 1;");   // current stage's B complete
        } else {
            asm volatile("cp.async.wait_group 0;");
        }
        __syncthreads();                      // A-gen + B visible to all warps

        const uint32_t Ab = sb + cb * 16384;
        const uint32_t Bb = sb + 32768 + cb * 16384;
#pragma unroll
        for (int ks = 0; ks < 4; ks++) {
            uint32_t a[4][4];
#pragma unroll
            for (int mt = 0; mt < 4; mt++) {
                uint32_t row = (uint32_t)(warpM * 64 + mt * 16) + lrow;
                ldsm_x4(Ab + sw128(row * 128 + ks * 32 + lkb), a[mt]);
            }
            uint32_t bf[2][4];
#pragma unroll
            for (int bt = 0; bt < 2; bt++) {
                uint32_t nrow = (uint32_t)(warpN * 32 + bt * 16) + lrow;
                ldsm_x4(Bb + sw128(nrow * 128 + ks * 32 + lkb), bf[bt]);
            }
#pragma unroll
            for (int mt = 0; mt < 4; mt++)
#pragma unroll
                for (int nt = 0; nt < 4; nt++) {
                    int bt = nt >> 1, hi = nt & 1;
                    mma16816(acc[mt][nt], a[mt], bf[bt][hi], bf[bt][hi + 2]);
                }
        }
        __syncthreads();                      // done reading cb before next gen overwrites
    }

    // epilogue: direct f32 stores
#pragma unroll
    for (int mt = 0; mt < 4; mt++) {
        int r0 = bb + warpM * 64 + mt * 16 + (lane >> 2);
#pragma unroll
        for (int nt = 0; nt < 4; nt++) {
            int c0 = ob + warpN * 32 + nt * 8 + (lane & 3) * 2;
            *(float2*)&out[(size_t)r0 * OUT_SZ + c0] =
                make_float2(acc[mt][nt][0], acc[mt][nt][1]);
            *(float2*)&out[(size_t)(r0 + 8) * OUT_SZ + c0] =
                make_float2(acc[mt][nt][2], acc[mt][nt][3]);
        }
    }
}

// ---------------------------------------------------------------------------
// Launch: x [8192,512], coeffs [512,512,21], base_w [512,512] -> out f32 [8192,512]
// ---------------------------------------------------------------------------
extern "C" void kernel_launch(void* const* d_in, const int* in_sizes, int n_in,
                              void* d_out, int out_size) {
    const float* x      = (const float*)d_in[0];
    const float* coeffs = (const float*)d_in[1];
    const float* base_w = (const float*)d_in[2];
    float* out = (float*)d_out;

    cudaFuncSetAttribute(kan_main, cudaFuncAttributeMaxDynamicSharedMemorySize, 65536);

    kan_params<<<dim3(B_SZ / 32, IN_SZ / 32), 256>>>(x);
    kan_cmat  <<<(OUT_SZ * KTOT / 8) / 256, 256>>>(coeffs, base_w);
    kan_main  <<<dim3(OUT_SZ / 128, B_SZ / 128), 256, 65536>>>(out);
}